// round 5
// baseline (speedup 1.0000x reference)
#include <cuda_runtime.h>
#include <cuda_fp16.h>
#include <math.h>

// ---------------------------------------------------------------------------
// ImbalancedGAT R5: fp16 gather table (halves agg1 L2 traffic), 4-edge/thread
// CSR build (MLP), self-loop planted by the scan, fused GEMM+alpha and
// fused agg1+layer2-transform retained from R4.
// ---------------------------------------------------------------------------

#define MAXN 65536
#define MAXE 4194304

__device__ __half  g_xw1h[MAXN * 128]; // layer1 transformed features (fp16)
__device__ float   g_as1[MAXN * 2];    // alpha_src layer1 (per head, fp32)
__device__ float   g_ad1[MAXN * 2];    // alpha_dst layer1
__device__ float4  g_n2[MAXN];         // {xw2_0, xw2_1, as2, ad2}
__device__ int     g_cnt[MAXN];
__device__ int     g_rowptr[MAXN + 1];
__device__ int     g_cursor[MAXN];
__device__ int     g_col[MAXE];        // CSR (self loop at row head)
__device__ int     g_is64;

__device__ __forceinline__ float lrelu(float x) { return x > 0.f ? x : 0.2f * x; }
__device__ __forceinline__ float elu(float x)   { return x > 0.f ? x : (expf(x) - 1.f); }

// ---- dtype detection for edge_index (int32 vs int64) ----------------------
__global__ void detect_kernel(const unsigned int* ew) {
    int lane = threadIdx.x;
    int nz = 0;
    for (int i = lane; i < 1024; i += 32) nz += (ew[2 * i + 1] != 0u);
    for (int o = 16; o; o >>= 1) nz += __shfl_xor_sync(0xffffffffu, nz, o);
    if (lane == 0) g_is64 = (nz == 0);  // all-zero high words => int64
}

__global__ void zero_kernel(int n) {
    int i = blockIdx.x * blockDim.x + threadIdx.x;
    if (i < n) g_cnt[i] = 0;
}

// ---- GEMM1 + alpha1 fused: xw1 = x @ W1 (fp16 out); as1/ad1 fp32 ----------
__global__ void __launch_bounds__(256) gemm1a_kernel(
        const float* __restrict__ x, const float* __restrict__ W,
        const float* __restrict__ a_src, const float* __restrict__ a_dst, int N) {
    __shared__ float xs[16][132];  // k-major: xs[k][row]
    __shared__ float ws[16][132];  // ws[k][col]
    int tid = threadIdx.x;
    int tx = tid & 15, ty = tid >> 4;
    int row0 = blockIdx.x * 128;

    float acc[8][8];
#pragma unroll
    for (int r = 0; r < 8; r++)
#pragma unroll
        for (int c = 0; c < 8; c++) acc[r][c] = 0.f;

    int lr = tid >> 1;            // x-load row 0..127
    int lk = (tid & 1) * 8;       // x-load k offset
    int gxr = row0 + lr; if (gxr >= N) gxr = N - 1;
    int wr = tid >> 4;            // W-load k row 0..15
    int wc = (tid & 15) * 8;      // W-load col

    for (int k0 = 0; k0 < 128; k0 += 16) {
        float4 v0 = *(const float4*)&x[(size_t)gxr * 128 + k0 + lk];
        float4 v1 = *(const float4*)&x[(size_t)gxr * 128 + k0 + lk + 4];
        xs[lk+0][lr] = v0.x; xs[lk+1][lr] = v0.y; xs[lk+2][lr] = v0.z; xs[lk+3][lr] = v0.w;
        xs[lk+4][lr] = v1.x; xs[lk+5][lr] = v1.y; xs[lk+6][lr] = v1.z; xs[lk+7][lr] = v1.w;
        float4 w0 = *(const float4*)&W[(size_t)(k0 + wr) * 128 + wc];
        float4 w1 = *(const float4*)&W[(size_t)(k0 + wr) * 128 + wc + 4];
        *(float4*)&ws[wr][wc]     = w0;
        *(float4*)&ws[wr][wc + 4] = w1;
        __syncthreads();
#pragma unroll
        for (int kk = 0; kk < 16; kk++) {
            float4 a0 = *(const float4*)&xs[kk][ty * 4];
            float4 a1 = *(const float4*)&xs[kk][64 + ty * 4];
            float4 b0 = *(const float4*)&ws[kk][tx * 4];
            float4 b1 = *(const float4*)&ws[kk][64 + tx * 4];
            float av[8] = {a0.x,a0.y,a0.z,a0.w, a1.x,a1.y,a1.z,a1.w};
            float bv[8] = {b0.x,b0.y,b0.z,b0.w, b1.x,b1.y,b1.z,b1.w};
#pragma unroll
            for (int r = 0; r < 8; r++)
#pragma unroll
                for (int c = 0; c < 8; c++) acc[r][c] += av[r] * bv[c];
        }
        __syncthreads();
    }

    float asv[8], adv[8];
#pragma unroll
    for (int c = 0; c < 4; c++) {
        asv[c]     = a_src[tx * 4 + c];      adv[c]     = a_dst[tx * 4 + c];
        asv[c + 4] = a_src[64 + tx * 4 + c]; adv[c + 4] = a_dst[64 + tx * 4 + c];
    }

#pragma unroll
    for (int r = 0; r < 8; r++) {
        int row = row0 + ((r < 4) ? (ty * 4 + r) : (64 + ty * 4 + r - 4));
        if (row < N) {
            __half2 p0 = __floats2half2_rn(acc[r][0], acc[r][1]);
            __half2 p1 = __floats2half2_rn(acc[r][2], acc[r][3]);
            __half2 p2 = __floats2half2_rn(acc[r][4], acc[r][5]);
            __half2 p3 = __floats2half2_rn(acc[r][6], acc[r][7]);
            *(__half2*)&g_xw1h[(size_t)row * 128 + tx * 4]          = p0;
            *(__half2*)&g_xw1h[(size_t)row * 128 + tx * 4 + 2]      = p1;
            *(__half2*)&g_xw1h[(size_t)row * 128 + 64 + tx * 4]     = p2;
            *(__half2*)&g_xw1h[(size_t)row * 128 + 64 + tx * 4 + 2] = p3;
        }
        float ps0 = acc[r][0]*asv[0] + acc[r][1]*asv[1] + acc[r][2]*asv[2] + acc[r][3]*asv[3];
        float ps1 = acc[r][4]*asv[4] + acc[r][5]*asv[5] + acc[r][6]*asv[6] + acc[r][7]*asv[7];
        float pd0 = acc[r][0]*adv[0] + acc[r][1]*adv[1] + acc[r][2]*adv[2] + acc[r][3]*adv[3];
        float pd1 = acc[r][4]*adv[4] + acc[r][5]*adv[5] + acc[r][6]*adv[6] + acc[r][7]*adv[7];
#pragma unroll
        for (int o = 1; o < 16; o <<= 1) {
            ps0 += __shfl_xor_sync(0xffffffffu, ps0, o);
            ps1 += __shfl_xor_sync(0xffffffffu, ps1, o);
            pd0 += __shfl_xor_sync(0xffffffffu, pd0, o);
            pd1 += __shfl_xor_sync(0xffffffffu, pd1, o);
        }
        if (tx == 0 && row < N) {
            g_as1[2 * row]     = ps0;
            g_as1[2 * row + 1] = ps1;
            g_ad1[2 * row]     = pd0;
            g_ad1[2 * row + 1] = pd1;
        }
    }
}

// ---- CSR build: 4 edges per thread for MLP --------------------------------
__global__ void hist_kernel(const void* e, int E) {
    int base = (blockIdx.x * blockDim.x + threadIdx.x) * 4;
    if (base >= E) return;
    int d[4];
    int n = E - base; if (n > 4) n = 4;
    if (g_is64) {
        const long long* p = (const long long*)e + E + base;
        if (n == 4) {
            longlong2 v0 = *(const longlong2*)p;
            longlong2 v1 = *(const longlong2*)(p + 2);
            d[0]=(int)v0.x; d[1]=(int)v0.y; d[2]=(int)v1.x; d[3]=(int)v1.y;
        } else {
            for (int i = 0; i < n; i++) d[i] = (int)p[i];
        }
    } else {
        const int* p = (const int*)e + E + base;
        if (n == 4) {
            int4 v = *(const int4*)p;
            d[0]=v.x; d[1]=v.y; d[2]=v.z; d[3]=v.w;
        } else {
            for (int i = 0; i < n; i++) d[i] = p[i];
        }
    }
    for (int i = 0; i < n; i++) atomicAdd(&g_cnt[d[i]], 1);
}

// warp-shuffle scan; +1 per node folds self-loop into CSR at the row head.
__global__ void scan_kernel(int n) {
    __shared__ int wsum[32];
    __shared__ int carry_sh;
    int t = threadIdx.x, lane = t & 31, wid = t >> 5;
    if (t == 0) carry_sh = 0;
    __syncthreads();
    for (int base = 0; base < n; base += 1024) {
        int idx = base + t;
        int v = (idx < n) ? (g_cnt[idx] + 1) : 0;
        int s = v;
#pragma unroll
        for (int o = 1; o < 32; o <<= 1) {
            int u = __shfl_up_sync(0xffffffffu, s, o);
            if (lane >= o) s += u;
        }
        if (lane == 31) wsum[wid] = s;
        __syncthreads();
        if (wid == 0) {
            int w = wsum[lane];
#pragma unroll
            for (int o = 1; o < 32; o <<= 1) {
                int u = __shfl_up_sync(0xffffffffu, w, o);
                if (lane >= o) w += u;
            }
            wsum[lane] = w;
        }
        __syncthreads();
        int off = carry_sh + (wid ? wsum[wid - 1] : 0);
        int excl = off + s - v;
        if (idx < n) {
            g_rowptr[idx] = excl;
            g_col[excl]   = idx;       // self loop at row head
            g_cursor[idx] = excl + 1;
        }
        __syncthreads();
        if (t == 0) carry_sh += wsum[31];
        __syncthreads();
    }
    if (t == 0) g_rowptr[n] = carry_sh;
}

__global__ void fill_kernel(const void* e, int E) {
    int base = (blockIdx.x * blockDim.x + threadIdx.x) * 4;
    if (base >= E) return;
    int s[4], d[4];
    int n = E - base; if (n > 4) n = 4;
    if (g_is64) {
        const long long* ps = (const long long*)e + base;
        const long long* pd = (const long long*)e + E + base;
        if (n == 4) {
            longlong2 s0 = *(const longlong2*)ps, s1 = *(const longlong2*)(ps + 2);
            longlong2 d0 = *(const longlong2*)pd, d1 = *(const longlong2*)(pd + 2);
            s[0]=(int)s0.x; s[1]=(int)s0.y; s[2]=(int)s1.x; s[3]=(int)s1.y;
            d[0]=(int)d0.x; d[1]=(int)d0.y; d[2]=(int)d1.x; d[3]=(int)d1.y;
        } else {
            for (int i = 0; i < n; i++) { s[i]=(int)ps[i]; d[i]=(int)pd[i]; }
        }
    } else {
        const int* ps = (const int*)e + base;
        const int* pd = (const int*)e + E + base;
        if (n == 4) {
            int4 sv = *(const int4*)ps, dv = *(const int4*)pd;
            s[0]=sv.x; s[1]=sv.y; s[2]=sv.z; s[3]=sv.w;
            d[0]=dv.x; d[1]=dv.y; d[2]=dv.z; d[3]=dv.w;
        } else {
            for (int i = 0; i < n; i++) { s[i]=ps[i]; d[i]=pd[i]; }
        }
    }
    for (int i = 0; i < n; i++)
        g_col[atomicAdd(&g_cursor[d[i]], 1)] = s[i];
}

// ---- Layer1 aggregation (single-pass softmax) + fused layer2 transform ----
__global__ void __launch_bounds__(256) agg1_kernel(
        const float* __restrict__ b1, const float* __restrict__ W2,
        const float* __restrict__ a_src2, const float* __restrict__ a_dst2, int N) {
    __shared__ int   s_sh [8][32];
    __shared__ float w0_sh[8][32];
    __shared__ float w1_sh[8][32];
    int wip  = threadIdx.x >> 5;
    int lane = threadIdx.x & 31;
    int d = blockIdx.x * 8 + wip;
    if (d >= N) return;
    int start = g_rowptr[d], end = g_rowptr[d + 1];
    float ad0 = g_ad1[2 * d], ad1 = g_ad1[2 * d + 1];
    int c = lane * 4;
    int head = (c >= 64);
    float4 accA = make_float4(0.f, 0.f, 0.f, 0.f);
    float4 accB = make_float4(0.f, 0.f, 0.f, 0.f);
    float ds0 = 0.f, ds1 = 0.f;
    int*   ss  = s_sh [wip];
    float* w0s = w0_sh[wip];
    float* w1s = w1_sh[wip];

    for (int base = start; base < end; base += 32) {
        int i = base + lane;
        int s = d; float w0 = 0.f, w1 = 0.f;
        if (i < end) {
            s = g_col[i];
            float2 a = *(const float2*)&g_as1[2 * s];
            w0 = expf(lrelu(a.x + ad0));   // no max: logits bounded
            w1 = expf(lrelu(a.y + ad1));
            ds0 += w0; ds1 += w1;
        }
        __syncwarp();
        ss[lane] = s; w0s[lane] = w0; w1s[lane] = w1;
        __syncwarp();
        int cnt = end - base; if (cnt > 32) cnt = 32;
        int g = 0;
        for (; g + 4 <= cnt; g += 4) {
            int4   s4 = *(const int4*)&ss[g];
            float4 w4 = head ? *(const float4*)&w1s[g] : *(const float4*)&w0s[g];
            uint2 r0 = *(const uint2*)&g_xw1h[(size_t)s4.x * 128 + c];
            uint2 r1 = *(const uint2*)&g_xw1h[(size_t)s4.y * 128 + c];
            uint2 r2 = *(const uint2*)&g_xw1h[(size_t)s4.z * 128 + c];
            uint2 r3 = *(const uint2*)&g_xw1h[(size_t)s4.w * 128 + c];
            float2 v0a = __half22float2(*(__half2*)&r0.x), v0b = __half22float2(*(__half2*)&r0.y);
            float2 v1a = __half22float2(*(__half2*)&r1.x), v1b = __half22float2(*(__half2*)&r1.y);
            float2 v2a = __half22float2(*(__half2*)&r2.x), v2b = __half22float2(*(__half2*)&r2.y);
            float2 v3a = __half22float2(*(__half2*)&r3.x), v3b = __half22float2(*(__half2*)&r3.y);
            accA.x += w4.x * v0a.x; accA.y += w4.x * v0a.y; accA.z += w4.x * v0b.x; accA.w += w4.x * v0b.y;
            accB.x += w4.y * v1a.x; accB.y += w4.y * v1a.y; accB.z += w4.y * v1b.x; accB.w += w4.y * v1b.y;
            accA.x += w4.z * v2a.x; accA.y += w4.z * v2a.y; accA.z += w4.z * v2b.x; accA.w += w4.z * v2b.y;
            accB.x += w4.w * v3a.x; accB.y += w4.w * v3a.y; accB.z += w4.w * v3b.x; accB.w += w4.w * v3b.y;
        }
        for (; g < cnt; g++) {
            int   sk = ss[g];
            float wk = head ? w1s[g] : w0s[g];
            uint2 r = *(const uint2*)&g_xw1h[(size_t)sk * 128 + c];
            float2 va = __half22float2(*(__half2*)&r.x), vb = __half22float2(*(__half2*)&r.y);
            accA.x += wk * va.x; accA.y += wk * va.y; accA.z += wk * vb.x; accA.w += wk * vb.y;
        }
    }
#pragma unroll
    for (int o = 16; o; o >>= 1) {
        ds0 += __shfl_xor_sync(0xffffffffu, ds0, o);
        ds1 += __shfl_xor_sync(0xffffffffu, ds1, o);
    }
    float denom = (head ? ds1 : ds0) + 1e-16f;
    float inv = 1.f / denom;
    float4 bb = *(const float4*)&b1[c];
    float4 h;
    h.x = elu((accA.x + accB.x) * inv + bb.x);
    h.y = elu((accA.y + accB.y) * inv + bb.y);
    h.z = elu((accA.z + accB.z) * inv + bb.z);
    h.w = elu((accA.w + accB.w) * inv + bb.w);

    // fused layer2 transform: p = h . W2[128,2]
    float p0 = h.x * W2[2*(c+0)]   + h.y * W2[2*(c+1)]   + h.z * W2[2*(c+2)]   + h.w * W2[2*(c+3)];
    float p1 = h.x * W2[2*(c+0)+1] + h.y * W2[2*(c+1)+1] + h.z * W2[2*(c+2)+1] + h.w * W2[2*(c+3)+1];
#pragma unroll
    for (int o = 16; o; o >>= 1) {
        p0 += __shfl_xor_sync(0xffffffffu, p0, o);
        p1 += __shfl_xor_sync(0xffffffffu, p1, o);
    }
    if (lane == 0) {
        float4 nv;
        nv.x = p0; nv.y = p1;
        nv.z = p0 * a_src2[0] + p1 * a_src2[1];
        nv.w = p0 * a_dst2[0] + p1 * a_dst2[1];
        g_n2[d] = nv;
    }
}

// ---- Layer2 aggregation: warp per dst node, single pass -------------------
__global__ void agg2_kernel(const float* __restrict__ b2, float* __restrict__ out, int N) {
    int warp = (blockIdx.x * blockDim.x + threadIdx.x) >> 5;
    int lane = threadIdx.x & 31;
    if (warp >= N) return;
    int d = warp;
    int start = g_rowptr[d], end = g_rowptr[d + 1];
    float adv = g_n2[d].w;
    float a0 = 0.f, a1 = 0.f, ds = 0.f;
    for (int i = start + lane; i < end; i += 32) {
        float4 nv = g_n2[g_col[i]];
        float w = expf(lrelu(nv.z + adv));
        ds += w; a0 += w * nv.x; a1 += w * nv.y;
    }
#pragma unroll
    for (int o = 16; o; o >>= 1) {
        a0 += __shfl_xor_sync(0xffffffffu, a0, o);
        a1 += __shfl_xor_sync(0xffffffffu, a1, o);
        ds += __shfl_xor_sync(0xffffffffu, ds, o);
    }
    if (lane == 0) {
        float inv = 1.f / (ds + 1e-16f);
        out[2 * d]     = a0 * inv + b2[0];
        out[2 * d + 1] = a1 * inv + b2[1];
    }
}

// ---------------------------------------------------------------------------
extern "C" void kernel_launch(void* const* d_in, const int* in_sizes, int n_in,
                              void* d_out, int out_size) {
    const float* x    = (const float*)d_in[0];
    const void*  eidx = d_in[1];
    const float* W1   = (const float*)d_in[2];
    const float* as1  = (const float*)d_in[3];
    const float* ad1  = (const float*)d_in[4];
    const float* b1   = (const float*)d_in[5];
    const float* W2   = (const float*)d_in[6];
    const float* as2  = (const float*)d_in[7];
    const float* ad2  = (const float*)d_in[8];
    const float* b2   = (const float*)d_in[9];

    int N = in_sizes[0] / 128;
    int E = in_sizes[1] / 2;
    int nt4 = (E + 3) / 4;  // threads at 4 edges each

    detect_kernel<<<1, 32>>>((const unsigned int*)eidx);
    zero_kernel<<<(N + 255) / 256, 256>>>(N);
    gemm1a_kernel<<<(N + 127) / 128, 256>>>(x, W1, as1, ad1, N);
    hist_kernel<<<(nt4 + 255) / 256, 256>>>(eidx, E);
    scan_kernel<<<1, 1024>>>(N);
    fill_kernel<<<(nt4 + 255) / 256, 256>>>(eidx, E);
    agg1_kernel<<<(N + 7) / 8, 256>>>(b1, W2, as2, ad2, N);
    agg2_kernel<<<(N + 7) / 8, 256>>>(b2, (float*)d_out, N);
}

// round 6
// speedup vs baseline: 1.1856x; 1.1856x over previous
#include <cuda_runtime.h>
#include <cuda_fp16.h>
#include <math.h>
#include <stdint.h>

// ---------------------------------------------------------------------------
// ImbalancedGAT R6: tensor-core GEMM1 (mma.sync m16n8k16 fp16->fp32) with
// fused fp32 alpha epilogue; fp16 gather table; 2-edge/thread CSR build;
// self-loop planted by scan. gemm1a moved to launch index 3 for profiling.
// ---------------------------------------------------------------------------

#define MAXN 65536
#define MAXE 4194304

__device__ __half  g_xw1h[MAXN * 128]; // layer1 transformed features (fp16)
__device__ float   g_as1[MAXN * 2];    // alpha_src layer1 (per head, fp32)
__device__ float   g_ad1[MAXN * 2];    // alpha_dst layer1
__device__ float4  g_n2[MAXN];         // {xw2_0, xw2_1, as2, ad2}
__device__ int     g_cnt[MAXN];
__device__ int     g_rowptr[MAXN + 1];
__device__ int     g_cursor[MAXN];
__device__ int     g_col[MAXE];        // CSR (self loop at row head)
__device__ int     g_is64;

__device__ __forceinline__ float lrelu(float x) { return x > 0.f ? x : 0.2f * x; }
__device__ __forceinline__ float elu(float x)   { return x > 0.f ? x : (expf(x) - 1.f); }

// ---- dtype detection for edge_index (int32 vs int64) ----------------------
__global__ void detect_kernel(const unsigned int* ew) {
    int lane = threadIdx.x;
    int nz = 0;
    for (int i = lane; i < 1024; i += 32) nz += (ew[2 * i + 1] != 0u);
    for (int o = 16; o; o >>= 1) nz += __shfl_xor_sync(0xffffffffu, nz, o);
    if (lane == 0) g_is64 = (nz == 0);  // all-zero high words => int64
}

__global__ void zero_kernel(int n) {
    int i = blockIdx.x * blockDim.x + threadIdx.x;
    if (i < n) g_cnt[i] = 0;
}

// ---- mma helpers ----------------------------------------------------------
__device__ __forceinline__ void ldsm_x4(uint32_t addr, uint32_t* r) {
    asm volatile("ldmatrix.sync.aligned.m8n8.x4.shared.b16 {%0,%1,%2,%3}, [%4];"
                 : "=r"(r[0]), "=r"(r[1]), "=r"(r[2]), "=r"(r[3]) : "r"(addr));
}
__device__ __forceinline__ void ldsm_x4_t(uint32_t addr, uint32_t* r) {
    asm volatile("ldmatrix.sync.aligned.m8n8.x4.trans.shared.b16 {%0,%1,%2,%3}, [%4];"
                 : "=r"(r[0]), "=r"(r[1]), "=r"(r[2]), "=r"(r[3]) : "r"(addr));
}
__device__ __forceinline__ void mma16816(float* c, const uint32_t* a, const uint32_t* b) {
    asm volatile("mma.sync.aligned.m16n8k16.row.col.f32.f16.f16.f32 "
                 "{%0,%1,%2,%3}, {%4,%5,%6,%7}, {%8,%9}, {%0,%1,%2,%3};"
                 : "+f"(c[0]), "+f"(c[1]), "+f"(c[2]), "+f"(c[3])
                 : "r"(a[0]), "r"(a[1]), "r"(a[2]), "r"(a[3]), "r"(b[0]), "r"(b[1]));
}

// ---- GEMM1 + alpha1 fused (tensor cores) ----------------------------------
// Block: 128 rows x 128 cols, 256 thr / 8 warps. Warp tile 32x64.
// K=128 in 2 chunks of 64. xs[128][72] fp16, ws[64][136] fp16; output staged
// through os[128][136] fp16 for coalesced stores. Alpha from fp32 accs.
#define XS_STRIDE 72
#define WS_STRIDE 136
#define OS_STRIDE 136
#define XS_BYTES  (128 * XS_STRIDE * 2)     // 18432
#define SM_BYTES  (XS_BYTES + 64 * WS_STRIDE * 2)  // 35840

__global__ void __launch_bounds__(256) gemm1a_kernel(
        const float* __restrict__ x, const float* __restrict__ W,
        const float* __restrict__ a_src, const float* __restrict__ a_dst, int N) {
    __shared__ __align__(16) unsigned char smbuf[SM_BYTES];
    __half* xs = (__half*)smbuf;                 // [128][72]
    __half* ws = (__half*)(smbuf + XS_BYTES);    // [64][136]
    __half* os = (__half*)smbuf;                 // [128][136] (reused)

    int tid  = threadIdx.x;
    int lane = tid & 31;
    int wid  = tid >> 5;
    int row0 = blockIdx.x * 128;
    int R0 = (wid >> 1) * 32;      // warp row base
    int C0 = (wid & 1) * 64;       // warp col base (== head * 64)

    float acc[2][8][4];
#pragma unroll
    for (int mt = 0; mt < 2; mt++)
#pragma unroll
        for (int nt = 0; nt < 8; nt++)
#pragma unroll
            for (int c = 0; c < 4; c++) acc[mt][nt][c] = 0.f;

    uint32_t xs_base = (uint32_t)__cvta_generic_to_shared(xs);
    uint32_t ws_base = (uint32_t)__cvta_generic_to_shared(ws);

    for (int chunk = 0; chunk < 2; chunk++) {
        int k0 = chunk * 64;
        // load x[128][64] fp32 -> xs fp16 : 2048 float4s, 8 per thread
#pragma unroll
        for (int j = 0; j < 8; j++) {
            int i = tid + j * 256;
            int r = i >> 4, fc = i & 15;
            int gr = row0 + r; if (gr >= N) gr = N - 1;
            float4 v = *(const float4*)&x[(size_t)gr * 128 + k0 + fc * 4];
            __half2* dst = (__half2*)&xs[r * XS_STRIDE + fc * 4];
            dst[0] = __floats2half2_rn(v.x, v.y);
            dst[1] = __floats2half2_rn(v.z, v.w);
        }
        // load W[64][128] fp32 -> ws fp16 : 2048 float4s
#pragma unroll
        for (int j = 0; j < 8; j++) {
            int i = tid + j * 256;
            int r = i >> 5, fc = i & 31;
            float4 v = *(const float4*)&W[(size_t)(k0 + r) * 128 + fc * 4];
            __half2* dst = (__half2*)&ws[r * WS_STRIDE + fc * 4];
            dst[0] = __floats2half2_rn(v.x, v.y);
            dst[1] = __floats2half2_rn(v.z, v.w);
        }
        __syncthreads();
#pragma unroll
        for (int kt = 0; kt < 4; kt++) {
            uint32_t af[2][4];
#pragma unroll
            for (int mt = 0; mt < 2; mt++) {
                uint32_t addr = xs_base + 2 * ((R0 + mt * 16 + (lane & 15)) * XS_STRIDE
                                               + kt * 16 + (lane >> 4) * 8);
                ldsm_x4(addr, af[mt]);
            }
            uint32_t bf[4][4];
#pragma unroll
            for (int np = 0; np < 4; np++) {
                uint32_t addr = ws_base + 2 * ((kt * 16 + (lane & 15)) * WS_STRIDE
                                               + C0 + np * 16 + (lane >> 4) * 8);
                ldsm_x4_t(addr, bf[np]);
            }
#pragma unroll
            for (int mt = 0; mt < 2; mt++)
#pragma unroll
                for (int np = 0; np < 4; np++) {
                    mma16816(acc[mt][2 * np],     af[mt], &bf[np][0]);
                    mma16816(acc[mt][2 * np + 1], af[mt], &bf[np][2]);
                }
        }
        __syncthreads();
    }

    // ---- alpha epilogue (fp32, from accumulators) ----
    // lane's fixed cols: C0 + nt*8 + (lane&3)*2 + {0,1}
    float2 as_l[8], ad_l[8];
#pragma unroll
    for (int nt = 0; nt < 8; nt++) {
        int col = C0 + nt * 8 + (lane & 3) * 2;
        as_l[nt] = *(const float2*)&a_src[col];
        ad_l[nt] = *(const float2*)&a_dst[col];
    }
    int head = wid & 1;
#pragma unroll
    for (int mt = 0; mt < 2; mt++)
#pragma unroll
        for (int rh = 0; rh < 2; rh++) {
            float ps = 0.f, pd = 0.f;
#pragma unroll
            for (int nt = 0; nt < 8; nt++) {
                float v0 = acc[mt][nt][2 * rh], v1 = acc[mt][nt][2 * rh + 1];
                ps += v0 * as_l[nt].x + v1 * as_l[nt].y;
                pd += v0 * ad_l[nt].x + v1 * ad_l[nt].y;
            }
            ps += __shfl_xor_sync(0xffffffffu, ps, 1);
            pd += __shfl_xor_sync(0xffffffffu, pd, 1);
            ps += __shfl_xor_sync(0xffffffffu, ps, 2);
            pd += __shfl_xor_sync(0xffffffffu, pd, 2);
            if ((lane & 3) == 0) {
                int row = row0 + R0 + mt * 16 + rh * 8 + (lane >> 2);
                if (row < N) {
                    g_as1[2 * row + head] = ps;
                    g_ad1[2 * row + head] = pd;
                }
            }
        }

    // ---- stage output to smem (fp16), then coalesced global store ----
#pragma unroll
    for (int mt = 0; mt < 2; mt++)
#pragma unroll
        for (int nt = 0; nt < 8; nt++) {
            int r = R0 + mt * 16 + (lane >> 2);
            int cc = C0 + nt * 8 + (lane & 3) * 2;
            *(__half2*)&os[r * OS_STRIDE + cc] =
                __floats2half2_rn(acc[mt][nt][0], acc[mt][nt][1]);
            *(__half2*)&os[(r + 8) * OS_STRIDE + cc] =
                __floats2half2_rn(acc[mt][nt][2], acc[mt][nt][3]);
        }
    __syncthreads();
#pragma unroll
    for (int j = 0; j < 8; j++) {
        int i = tid + j * 256;
        int r = i >> 4, c8 = i & 15;
        int gr = row0 + r;
        if (gr < N) {
            float4 v = *(const float4*)&os[r * OS_STRIDE + c8 * 8];
            *(float4*)&g_xw1h[(size_t)gr * 128 + c8 * 8] = v;
        }
    }
}

// ---- CSR build: 2 edges per thread (R4 variant; best measured) ------------
__global__ void hist_kernel(const void* e, int E) {
    int t = blockIdx.x * blockDim.x + threadIdx.x;
    int np = E >> 1;
    if (t < np) {
        int d0, d1;
        if (g_is64) {
            longlong2 v = ((const longlong2*)((const char*)e + (size_t)E * 8))[t];
            d0 = (int)v.x; d1 = (int)v.y;
        } else {
            int2 v = ((const int2*)((const char*)e + (size_t)E * 4))[t];
            d0 = v.x; d1 = v.y;
        }
        atomicAdd(&g_cnt[d0], 1);
        atomicAdd(&g_cnt[d1], 1);
    } else if (t == np && (E & 1)) {
        int d = g_is64 ? (int)((const long long*)e)[(size_t)E + E - 1]
                       : ((const int*)e)[(size_t)E + E - 1];
        atomicAdd(&g_cnt[d], 1);
    }
}

// warp-shuffle scan; +1 per node folds self-loop into CSR at the row head.
__global__ void scan_kernel(int n) {
    __shared__ int wsum[32];
    __shared__ int carry_sh;
    int t = threadIdx.x, lane = t & 31, wid = t >> 5;
    if (t == 0) carry_sh = 0;
    __syncthreads();
    for (int base = 0; base < n; base += 1024) {
        int idx = base + t;
        int v = (idx < n) ? (g_cnt[idx] + 1) : 0;
        int s = v;
#pragma unroll
        for (int o = 1; o < 32; o <<= 1) {
            int u = __shfl_up_sync(0xffffffffu, s, o);
            if (lane >= o) s += u;
        }
        if (lane == 31) wsum[wid] = s;
        __syncthreads();
        if (wid == 0) {
            int w = wsum[lane];
#pragma unroll
            for (int o = 1; o < 32; o <<= 1) {
                int u = __shfl_up_sync(0xffffffffu, w, o);
                if (lane >= o) w += u;
            }
            wsum[lane] = w;
        }
        __syncthreads();
        int off = carry_sh + (wid ? wsum[wid - 1] : 0);
        int excl = off + s - v;
        if (idx < n) {
            g_rowptr[idx] = excl;
            g_col[excl]   = idx;       // self loop at row head
            g_cursor[idx] = excl + 1;
        }
        __syncthreads();
        if (t == 0) carry_sh += wsum[31];
        __syncthreads();
    }
    if (t == 0) g_rowptr[n] = carry_sh;
}

__global__ void fill_kernel(const void* e, int E) {
    int t = blockIdx.x * blockDim.x + threadIdx.x;
    int np = E >> 1;
    if (t < np) {
        int s0, s1, d0, d1;
        if (g_is64) {
            longlong2 sv = ((const longlong2*)e)[t];
            longlong2 dv = ((const longlong2*)((const char*)e + (size_t)E * 8))[t];
            s0 = (int)sv.x; s1 = (int)sv.y; d0 = (int)dv.x; d1 = (int)dv.y;
        } else {
            int2 sv = ((const int2*)e)[t];
            int2 dv = ((const int2*)((const char*)e + (size_t)E * 4))[t];
            s0 = sv.x; s1 = sv.y; d0 = dv.x; d1 = dv.y;
        }
        g_col[atomicAdd(&g_cursor[d0], 1)] = s0;
        g_col[atomicAdd(&g_cursor[d1], 1)] = s1;
    } else if (t == np && (E & 1)) {
        int s, d;
        if (g_is64) { s = (int)((const long long*)e)[E - 1];
                      d = (int)((const long long*)e)[(size_t)E + E - 1]; }
        else        { s = ((const int*)e)[E - 1];
                      d = ((const int*)e)[(size_t)E + E - 1]; }
        g_col[atomicAdd(&g_cursor[d], 1)] = s;
    }
}

// ---- Layer1 aggregation (single-pass softmax) + fused layer2 transform ----
__global__ void __launch_bounds__(256) agg1_kernel(
        const float* __restrict__ b1, const float* __restrict__ W2,
        const float* __restrict__ a_src2, const float* __restrict__ a_dst2, int N) {
    __shared__ int   s_sh [8][32];
    __shared__ float w0_sh[8][32];
    __shared__ float w1_sh[8][32];
    int wip  = threadIdx.x >> 5;
    int lane = threadIdx.x & 31;
    int d = blockIdx.x * 8 + wip;
    if (d >= N) return;
    int start = g_rowptr[d], end = g_rowptr[d + 1];
    float ad0 = g_ad1[2 * d], ad1 = g_ad1[2 * d + 1];
    int c = lane * 4;
    int head = (c >= 64);
    float4 accA = make_float4(0.f, 0.f, 0.f, 0.f);
    float4 accB = make_float4(0.f, 0.f, 0.f, 0.f);
    float ds0 = 0.f, ds1 = 0.f;
    int*   ss  = s_sh [wip];
    float* w0s = w0_sh[wip];
    float* w1s = w1_sh[wip];

    for (int base = start; base < end; base += 32) {
        int i = base + lane;
        int s = d; float w0 = 0.f, w1 = 0.f;
        if (i < end) {
            s = g_col[i];
            float2 a = *(const float2*)&g_as1[2 * s];
            w0 = expf(lrelu(a.x + ad0));   // no max: logits bounded
            w1 = expf(lrelu(a.y + ad1));
            ds0 += w0; ds1 += w1;
        }
        __syncwarp();
        ss[lane] = s; w0s[lane] = w0; w1s[lane] = w1;
        __syncwarp();
        int cnt = end - base; if (cnt > 32) cnt = 32;
        int g = 0;
        for (; g + 4 <= cnt; g += 4) {
            int4   s4 = *(const int4*)&ss[g];
            float4 w4 = head ? *(const float4*)&w1s[g] : *(const float4*)&w0s[g];
            uint2 r0 = *(const uint2*)&g_xw1h[(size_t)s4.x * 128 + c];
            uint2 r1 = *(const uint2*)&g_xw1h[(size_t)s4.y * 128 + c];
            uint2 r2 = *(const uint2*)&g_xw1h[(size_t)s4.z * 128 + c];
            uint2 r3 = *(const uint2*)&g_xw1h[(size_t)s4.w * 128 + c];
            float2 v0a = __half22float2(*(__half2*)&r0.x), v0b = __half22float2(*(__half2*)&r0.y);
            float2 v1a = __half22float2(*(__half2*)&r1.x), v1b = __half22float2(*(__half2*)&r1.y);
            float2 v2a = __half22float2(*(__half2*)&r2.x), v2b = __half22float2(*(__half2*)&r2.y);
            float2 v3a = __half22float2(*(__half2*)&r3.x), v3b = __half22float2(*(__half2*)&r3.y);
            accA.x += w4.x * v0a.x; accA.y += w4.x * v0a.y; accA.z += w4.x * v0b.x; accA.w += w4.x * v0b.y;
            accB.x += w4.y * v1a.x; accB.y += w4.y * v1a.y; accB.z += w4.y * v1b.x; accB.w += w4.y * v1b.y;
            accA.x += w4.z * v2a.x; accA.y += w4.z * v2a.y; accA.z += w4.z * v2b.x; accA.w += w4.z * v2b.y;
            accB.x += w4.w * v3a.x; accB.y += w4.w * v3a.y; accB.z += w4.w * v3b.x; accB.w += w4.w * v3b.y;
        }
        for (; g < cnt; g++) {
            int   sk = ss[g];
            float wk = head ? w1s[g] : w0s[g];
            uint2 r = *(const uint2*)&g_xw1h[(size_t)sk * 128 + c];
            float2 va = __half22float2(*(__half2*)&r.x), vb = __half22float2(*(__half2*)&r.y);
            accA.x += wk * va.x; accA.y += wk * va.y; accA.z += wk * vb.x; accA.w += wk * vb.y;
        }
    }
#pragma unroll
    for (int o = 16; o; o >>= 1) {
        ds0 += __shfl_xor_sync(0xffffffffu, ds0, o);
        ds1 += __shfl_xor_sync(0xffffffffu, ds1, o);
    }
    float denom = (head ? ds1 : ds0) + 1e-16f;
    float inv = 1.f / denom;
    float4 bb = *(const float4*)&b1[c];
    float4 h;
    h.x = elu((accA.x + accB.x) * inv + bb.x);
    h.y = elu((accA.y + accB.y) * inv + bb.y);
    h.z = elu((accA.z + accB.z) * inv + bb.z);
    h.w = elu((accA.w + accB.w) * inv + bb.w);

    // fused layer2 transform: p = h . W2[128,2]
    float p0 = h.x * W2[2*(c+0)]   + h.y * W2[2*(c+1)]   + h.z * W2[2*(c+2)]   + h.w * W2[2*(c+3)];
    float p1 = h.x * W2[2*(c+0)+1] + h.y * W2[2*(c+1)+1] + h.z * W2[2*(c+2)+1] + h.w * W2[2*(c+3)+1];
#pragma unroll
    for (int o = 16; o; o >>= 1) {
        p0 += __shfl_xor_sync(0xffffffffu, p0, o);
        p1 += __shfl_xor_sync(0xffffffffu, p1, o);
    }
    if (lane == 0) {
        float4 nv;
        nv.x = p0; nv.y = p1;
        nv.z = p0 * a_src2[0] + p1 * a_src2[1];
        nv.w = p0 * a_dst2[0] + p1 * a_dst2[1];
        g_n2[d] = nv;
    }
}

// ---- Layer2 aggregation: warp per dst node, single pass -------------------
__global__ void agg2_kernel(const float* __restrict__ b2, float* __restrict__ out, int N) {
    int warp = (blockIdx.x * blockDim.x + threadIdx.x) >> 5;
    int lane = threadIdx.x & 31;
    if (warp >= N) return;
    int d = warp;
    int start = g_rowptr[d], end = g_rowptr[d + 1];
    float adv = g_n2[d].w;
    float a0 = 0.f, a1 = 0.f, ds = 0.f;
    for (int i = start + lane; i < end; i += 32) {
        float4 nv = g_n2[g_col[i]];
        float w = expf(lrelu(nv.z + adv));
        ds += w; a0 += w * nv.x; a1 += w * nv.y;
    }
#pragma unroll
    for (int o = 16; o; o >>= 1) {
        a0 += __shfl_xor_sync(0xffffffffu, a0, o);
        a1 += __shfl_xor_sync(0xffffffffu, a1, o);
        ds += __shfl_xor_sync(0xffffffffu, ds, o);
    }
    if (lane == 0) {
        float inv = 1.f / (ds + 1e-16f);
        out[2 * d]     = a0 * inv + b2[0];
        out[2 * d + 1] = a1 * inv + b2[1];
    }
}

// ---------------------------------------------------------------------------
extern "C" void kernel_launch(void* const* d_in, const int* in_sizes, int n_in,
                              void* d_out, int out_size) {
    const float* x    = (const float*)d_in[0];
    const void*  eidx = d_in[1];
    const float* W1   = (const float*)d_in[2];
    const float* as1  = (const float*)d_in[3];
    const float* ad1  = (const float*)d_in[4];
    const float* b1   = (const float*)d_in[5];
    const float* W2   = (const float*)d_in[6];
    const float* as2  = (const float*)d_in[7];
    const float* ad2  = (const float*)d_in[8];
    const float* b2   = (const float*)d_in[9];

    int N = in_sizes[0] / 128;
    int E = in_sizes[1] / 2;
    int np = (E >> 1) + 1;

    zero_kernel<<<(N + 255) / 256, 256>>>(N);                   // 0
    detect_kernel<<<1, 32>>>((const unsigned int*)eidx);        // 1
    hist_kernel<<<(np + 255) / 256, 256>>>(eidx, E);            // 2
    gemm1a_kernel<<<(N + 127) / 128, 256>>>(x, W1, as1, ad1, N);// 3 <- profiled
    scan_kernel<<<1, 1024>>>(N);                                // 4
    fill_kernel<<<(np + 255) / 256, 256>>>(eidx, E);            // 5
    agg1_kernel<<<(N + 7) / 8, 256>>>(b1, W2, as2, ad2, N);     // 6
    agg2_kernel<<<(N + 7) / 8, 256>>>(b2, (float*)d_out, N);    // 7
}

// round 7
// speedup vs baseline: 1.3996x; 1.1805x over previous
#include <cuda_runtime.h>
#include <cuda_fp16.h>
#include <math.h>
#include <stdint.h>

// ---------------------------------------------------------------------------
// ImbalancedGAT R7: fp32 gather table (fp16 cvts in agg1 measured slower),
// head-split agg1 (2 warps/node -> 2x latency hiding, half work per warp),
// multi-block scan, TC GEMM with direct fp32 epilogue stores.
// ---------------------------------------------------------------------------

#define MAXN 65536
#define MAXE 4194304

__device__ float   g_xw1[MAXN * 128]; // layer1 transformed features (fp32)
__device__ float   g_as1[MAXN * 2];   // alpha_src layer1 (per head)
__device__ float   g_ad1[MAXN * 2];   // alpha_dst layer1
__device__ float4  g_n2[MAXN];        // {xw2_0, xw2_1, as2, ad2}
__device__ int     g_cnt[MAXN];
__device__ int     g_rowptr[MAXN + 1];
__device__ int     g_cursor[MAXN];
__device__ int     g_col[MAXE];       // CSR (self loop at row head)
__device__ int     g_bsum[64];
__device__ int     g_boff[64];
__device__ int     g_is64;

__device__ __forceinline__ float lrelu(float x) { return x > 0.f ? x : 0.2f * x; }
__device__ __forceinline__ float elu(float x)   { return x > 0.f ? x : (expf(x) - 1.f); }

// ---- dtype detection for edge_index (int32 vs int64) ----------------------
__global__ void detect_kernel(const unsigned int* ew) {
    int lane = threadIdx.x;
    int nz = 0;
    for (int i = lane; i < 1024; i += 32) nz += (ew[2 * i + 1] != 0u);
    for (int o = 16; o; o >>= 1) nz += __shfl_xor_sync(0xffffffffu, nz, o);
    if (lane == 0) g_is64 = (nz == 0);  // all-zero high words => int64
}

__global__ void zero_kernel(int n) {
    int i = blockIdx.x * blockDim.x + threadIdx.x;
    if (i < n) g_cnt[i] = 0;
}

// ---- mma helpers ----------------------------------------------------------
__device__ __forceinline__ void ldsm_x4(uint32_t addr, uint32_t* r) {
    asm volatile("ldmatrix.sync.aligned.m8n8.x4.shared.b16 {%0,%1,%2,%3}, [%4];"
                 : "=r"(r[0]), "=r"(r[1]), "=r"(r[2]), "=r"(r[3]) : "r"(addr));
}
__device__ __forceinline__ void ldsm_x4_t(uint32_t addr, uint32_t* r) {
    asm volatile("ldmatrix.sync.aligned.m8n8.x4.trans.shared.b16 {%0,%1,%2,%3}, [%4];"
                 : "=r"(r[0]), "=r"(r[1]), "=r"(r[2]), "=r"(r[3]) : "r"(addr));
}
__device__ __forceinline__ void mma16816(float* c, const uint32_t* a, const uint32_t* b) {
    asm volatile("mma.sync.aligned.m16n8k16.row.col.f32.f16.f16.f32 "
                 "{%0,%1,%2,%3}, {%4,%5,%6,%7}, {%8,%9}, {%0,%1,%2,%3};"
                 : "+f"(c[0]), "+f"(c[1]), "+f"(c[2]), "+f"(c[3])
                 : "r"(a[0]), "r"(a[1]), "r"(a[2]), "r"(a[3]), "r"(b[0]), "r"(b[1]));
}

// ---- GEMM1 + alpha1 fused (tensor cores), fp32 direct-store epilogue ------
#define XS_STRIDE 72
#define WS_STRIDE 136
#define XS_BYTES  (128 * XS_STRIDE * 2)
#define SM_BYTES  (XS_BYTES + 64 * WS_STRIDE * 2)

__global__ void __launch_bounds__(256) gemm1a_kernel(
        const float* __restrict__ x, const float* __restrict__ W,
        const float* __restrict__ a_src, const float* __restrict__ a_dst, int N) {
    __shared__ __align__(16) unsigned char smbuf[SM_BYTES];
    __half* xs = (__half*)smbuf;                 // [128][72]
    __half* ws = (__half*)(smbuf + XS_BYTES);    // [64][136]

    int tid  = threadIdx.x;
    int lane = tid & 31;
    int wid  = tid >> 5;
    int row0 = blockIdx.x * 128;
    int R0 = (wid >> 1) * 32;      // warp row base
    int C0 = (wid & 1) * 64;       // warp col base (== head * 64)

    float acc[2][8][4];
#pragma unroll
    for (int mt = 0; mt < 2; mt++)
#pragma unroll
        for (int nt = 0; nt < 8; nt++)
#pragma unroll
            for (int c = 0; c < 4; c++) acc[mt][nt][c] = 0.f;

    uint32_t xs_base = (uint32_t)__cvta_generic_to_shared(xs);
    uint32_t ws_base = (uint32_t)__cvta_generic_to_shared(ws);

    for (int chunk = 0; chunk < 2; chunk++) {
        int k0 = chunk * 64;
#pragma unroll
        for (int j = 0; j < 8; j++) {
            int i = tid + j * 256;
            int r = i >> 4, fc = i & 15;
            int gr = row0 + r; if (gr >= N) gr = N - 1;
            float4 v = *(const float4*)&x[(size_t)gr * 128 + k0 + fc * 4];
            __half2* dst = (__half2*)&xs[r * XS_STRIDE + fc * 4];
            dst[0] = __floats2half2_rn(v.x, v.y);
            dst[1] = __floats2half2_rn(v.z, v.w);
        }
#pragma unroll
        for (int j = 0; j < 8; j++) {
            int i = tid + j * 256;
            int r = i >> 5, fc = i & 31;
            float4 v = *(const float4*)&W[(size_t)(k0 + r) * 128 + fc * 4];
            __half2* dst = (__half2*)&ws[r * WS_STRIDE + fc * 4];
            dst[0] = __floats2half2_rn(v.x, v.y);
            dst[1] = __floats2half2_rn(v.z, v.w);
        }
        __syncthreads();
#pragma unroll
        for (int kt = 0; kt < 4; kt++) {
            uint32_t af[2][4];
#pragma unroll
            for (int mt = 0; mt < 2; mt++) {
                uint32_t addr = xs_base + 2 * ((R0 + mt * 16 + (lane & 15)) * XS_STRIDE
                                               + kt * 16 + (lane >> 4) * 8);
                ldsm_x4(addr, af[mt]);
            }
            uint32_t bf[4][4];
#pragma unroll
            for (int np = 0; np < 4; np++) {
                uint32_t addr = ws_base + 2 * ((kt * 16 + (lane & 15)) * WS_STRIDE
                                               + C0 + np * 16 + (lane >> 4) * 8);
                ldsm_x4_t(addr, bf[np]);
            }
#pragma unroll
            for (int mt = 0; mt < 2; mt++)
#pragma unroll
                for (int np = 0; np < 4; np++) {
                    mma16816(acc[mt][2 * np],     af[mt], &bf[np][0]);
                    mma16816(acc[mt][2 * np + 1], af[mt], &bf[np][2]);
                }
        }
        __syncthreads();
    }

    // ---- alpha epilogue (fp32 from accumulators) ----
    float2 as_l[8], ad_l[8];
#pragma unroll
    for (int nt = 0; nt < 8; nt++) {
        int col = C0 + nt * 8 + (lane & 3) * 2;
        as_l[nt] = *(const float2*)&a_src[col];
        ad_l[nt] = *(const float2*)&a_dst[col];
    }
    int head = wid & 1;
#pragma unroll
    for (int mt = 0; mt < 2; mt++)
#pragma unroll
        for (int rh = 0; rh < 2; rh++) {
            float ps = 0.f, pd = 0.f;
#pragma unroll
            for (int nt = 0; nt < 8; nt++) {
                float v0 = acc[mt][nt][2 * rh], v1 = acc[mt][nt][2 * rh + 1];
                ps += v0 * as_l[nt].x + v1 * as_l[nt].y;
                pd += v0 * ad_l[nt].x + v1 * ad_l[nt].y;
            }
            ps += __shfl_xor_sync(0xffffffffu, ps, 1);
            pd += __shfl_xor_sync(0xffffffffu, pd, 1);
            ps += __shfl_xor_sync(0xffffffffu, ps, 2);
            pd += __shfl_xor_sync(0xffffffffu, pd, 2);
            if ((lane & 3) == 0) {
                int row = row0 + R0 + mt * 16 + rh * 8 + (lane >> 2);
                if (row < N) {
                    g_as1[2 * row + head] = ps;
                    g_ad1[2 * row + head] = pd;
                }
            }
        }

    // ---- direct fp32 stores (float2 per fragment; 32B sectors per row) ----
#pragma unroll
    for (int mt = 0; mt < 2; mt++)
#pragma unroll
        for (int nt = 0; nt < 8; nt++) {
            int r  = row0 + R0 + mt * 16 + (lane >> 2);
            int cc = C0 + nt * 8 + (lane & 3) * 2;
            if (r < N)
                *(float2*)&g_xw1[(size_t)r * 128 + cc] =
                    make_float2(acc[mt][nt][0], acc[mt][nt][1]);
            if (r + 8 < N)
                *(float2*)&g_xw1[(size_t)(r + 8) * 128 + cc] =
                    make_float2(acc[mt][nt][2], acc[mt][nt][3]);
        }
}

// ---- CSR build: 2 edges per thread ----------------------------------------
__global__ void hist_kernel(const void* e, int E) {
    int t = blockIdx.x * blockDim.x + threadIdx.x;
    int np = E >> 1;
    if (t < np) {
        int d0, d1;
        if (g_is64) {
            longlong2 v = ((const longlong2*)((const char*)e + (size_t)E * 8))[t];
            d0 = (int)v.x; d1 = (int)v.y;
        } else {
            int2 v = ((const int2*)((const char*)e + (size_t)E * 4))[t];
            d0 = v.x; d1 = v.y;
        }
        atomicAdd(&g_cnt[d0], 1);
        atomicAdd(&g_cnt[d1], 1);
    } else if (t == np && (E & 1)) {
        int d = g_is64 ? (int)((const long long*)e)[(size_t)E + E - 1]
                       : ((const int*)e)[(size_t)E + E - 1];
        atomicAdd(&g_cnt[d], 1);
    }
}

// ---- multi-block scan (+1 per node folds self-loop) -----------------------
__global__ void scan1_kernel(int n) {
    __shared__ int wsum[32];
    int t = threadIdx.x, lane = t & 31, wid = t >> 5;
    int idx = blockIdx.x * 1024 + t;
    int v = (idx < n) ? (g_cnt[idx] + 1) : 0;
    int s = v;
#pragma unroll
    for (int o = 1; o < 32; o <<= 1) {
        int u = __shfl_up_sync(0xffffffffu, s, o);
        if (lane >= o) s += u;
    }
    if (lane == 31) wsum[wid] = s;
    __syncthreads();
    if (wid == 0) {
        int w = wsum[lane];
#pragma unroll
        for (int o = 1; o < 32; o <<= 1) {
            int u = __shfl_up_sync(0xffffffffu, w, o);
            if (lane >= o) w += u;
        }
        wsum[lane] = w;
    }
    __syncthreads();
    int incl = s + (wid ? wsum[wid - 1] : 0);
    if (idx < n) g_cursor[idx] = incl;         // block-local inclusive (tmp)
    if (t == 0) g_bsum[blockIdx.x] = wsum[31]; // block total
}

__global__ void scan2_kernel(int nb, int n) {
    __shared__ int wsum[32];
    int t = threadIdx.x, lane = t & 31, wid = t >> 5;
    int v = (t < nb) ? g_bsum[t] : 0;
    int s = v;
#pragma unroll
    for (int o = 1; o < 32; o <<= 1) {
        int u = __shfl_up_sync(0xffffffffu, s, o);
        if (lane >= o) s += u;
    }
    if (lane == 31) wsum[wid] = s;
    __syncthreads();
    if (wid == 0) {
        int w = wsum[lane];
#pragma unroll
        for (int o = 1; o < 32; o <<= 1) {
            int u = __shfl_up_sync(0xffffffffu, w, o);
            if (lane >= o) w += u;
        }
        wsum[lane] = w;
    }
    __syncthreads();
    int incl = s + (wid ? wsum[wid - 1] : 0);
    if (t < nb) g_boff[t] = incl - v;          // exclusive block offset
    if (t == nb - 1) g_rowptr[n] = incl;       // total
}

__global__ void scan3_kernel(int n) {
    int idx = blockIdx.x * 1024 + threadIdx.x;
    if (idx >= n) return;
    int v = g_cnt[idx] + 1;
    int incl = g_cursor[idx];
    int excl = g_boff[idx >> 10] + incl - v;
    g_rowptr[idx] = excl;
    g_col[excl]   = idx;        // self loop at row head
    g_cursor[idx] = excl + 1;
}

__global__ void fill_kernel(const void* e, int E) {
    int t = blockIdx.x * blockDim.x + threadIdx.x;
    int np = E >> 1;
    if (t < np) {
        int s0, s1, d0, d1;
        if (g_is64) {
            longlong2 sv = ((const longlong2*)e)[t];
            longlong2 dv = ((const longlong2*)((const char*)e + (size_t)E * 8))[t];
            s0 = (int)sv.x; s1 = (int)sv.y; d0 = (int)dv.x; d1 = (int)dv.y;
        } else {
            int2 sv = ((const int2*)e)[t];
            int2 dv = ((const int2*)((const char*)e + (size_t)E * 4))[t];
            s0 = sv.x; s1 = sv.y; d0 = dv.x; d1 = dv.y;
        }
        g_col[atomicAdd(&g_cursor[d0], 1)] = s0;
        g_col[atomicAdd(&g_cursor[d1], 1)] = s1;
    } else if (t == np && (E & 1)) {
        int s, d;
        if (g_is64) { s = (int)((const long long*)e)[E - 1];
                      d = (int)((const long long*)e)[(size_t)E + E - 1]; }
        else        { s = ((const int*)e)[E - 1];
                      d = ((const int*)e)[(size_t)E + E - 1]; }
        g_col[atomicAdd(&g_cursor[d], 1)] = s;
    }
}

// ---- Layer1 aggregation: 2 warps per node (one per head) ------------------
// Warp lanes split into 2 groups of 16; each group handles one edge at a
// time over the head's 64 channels (16 lanes x float4). Zero-weight padding
// rounds chunks to multiples of 4 (no remainder loop). Fused layer2
// transform combines both heads via smem.
__global__ void __launch_bounds__(256) agg1_kernel(
        const float* __restrict__ b1, const float* __restrict__ W2,
        const float* __restrict__ a_src2, const float* __restrict__ a_dst2, int N) {
    __shared__ int   s_sh[8][32];
    __shared__ float w_sh[8][32];
    __shared__ float p_sh[8][2];
    int wip  = threadIdx.x >> 5;
    int lane = threadIdx.x & 31;
    int d    = blockIdx.x * 4 + (wip >> 1);
    int head = wip & 1;
    bool valid = d < N;

    if (valid) {
        int start = g_rowptr[d], end = g_rowptr[d + 1];
        float adv = g_ad1[2 * d + head];
        int grp = lane >> 4;
        int cq  = (lane & 15) * 4;
        const float* bx = g_xw1 + head * 64 + cq;
        float4 accA = make_float4(0.f, 0.f, 0.f, 0.f);
        float4 accB = make_float4(0.f, 0.f, 0.f, 0.f);
        float ds = 0.f;
        int*   ss = s_sh[wip];
        float* ws = w_sh[wip];

        for (int b0 = start; b0 < end; b0 += 32) {
            int i = b0 + lane;
            int s = d; float w = 0.f;
            if (i < end) {
                s = g_col[i];
                w = expf(lrelu(g_as1[2 * s + head] + adv));  // no max: bounded
                ds += w;
            }
            __syncwarp();
            ss[lane] = s; ws[lane] = w;
            __syncwarp();
            int cnt = end - b0; if (cnt > 32) cnt = 32;
            cnt = (cnt + 3) & ~3;                  // pad: w=0 entries no-op
            for (int g = 0; g < cnt; g += 4) {
                int4   s4 = *(const int4*)&ss[g];
                float4 w4 = *(const float4*)&ws[g];
                int   sA = grp ? s4.y : s4.x;
                int   sB = grp ? s4.w : s4.z;
                float wA = grp ? w4.y : w4.x;
                float wB = grp ? w4.w : w4.z;
                float4 vA = *(const float4*)&bx[(size_t)sA * 128];
                float4 vB = *(const float4*)&bx[(size_t)sB * 128];
                accA.x += wA * vA.x; accA.y += wA * vA.y;
                accA.z += wA * vA.z; accA.w += wA * vA.w;
                accB.x += wB * vB.x; accB.y += wB * vB.y;
                accB.z += wB * vB.z; accB.w += wB * vB.w;
            }
        }
        // merge the two 16-lane groups
        accA.x += accB.x; accA.y += accB.y; accA.z += accB.z; accA.w += accB.w;
        accA.x += __shfl_xor_sync(0xffffffffu, accA.x, 16);
        accA.y += __shfl_xor_sync(0xffffffffu, accA.y, 16);
        accA.z += __shfl_xor_sync(0xffffffffu, accA.z, 16);
        accA.w += __shfl_xor_sync(0xffffffffu, accA.w, 16);
#pragma unroll
        for (int o = 16; o; o >>= 1)
            ds += __shfl_xor_sync(0xffffffffu, ds, o);
        float inv = 1.f / (ds + 1e-16f);
        int cg = head * 64 + cq;
        float4 bb = *(const float4*)&b1[cg];
        float hx = elu(accA.x * inv + bb.x);
        float hy = elu(accA.y * inv + bb.y);
        float hz = elu(accA.z * inv + bb.z);
        float hw = elu(accA.w * inv + bb.w);
        // fused layer2 transform partials over this head's channels
        float p0 = hx * W2[2*cg]   + hy * W2[2*(cg+1)]   + hz * W2[2*(cg+2)]   + hw * W2[2*(cg+3)];
        float p1 = hx * W2[2*cg+1] + hy * W2[2*(cg+1)+1] + hz * W2[2*(cg+2)+1] + hw * W2[2*(cg+3)+1];
#pragma unroll
        for (int o = 1; o < 16; o <<= 1) {
            p0 += __shfl_xor_sync(0xffffffffu, p0, o);
            p1 += __shfl_xor_sync(0xffffffffu, p1, o);
        }
        if (lane == 0) { p_sh[wip][0] = p0; p_sh[wip][1] = p1; }
    }
    __syncthreads();
    if (valid && head == 0 && lane == 0) {
        float q0 = p_sh[wip][0] + p_sh[wip + 1][0];
        float q1 = p_sh[wip][1] + p_sh[wip + 1][1];
        float4 nv;
        nv.x = q0; nv.y = q1;
        nv.z = q0 * a_src2[0] + q1 * a_src2[1];
        nv.w = q0 * a_dst2[0] + q1 * a_dst2[1];
        g_n2[d] = nv;
    }
}

// ---- Layer2 aggregation: warp per dst node, single pass -------------------
__global__ void agg2_kernel(const float* __restrict__ b2, float* __restrict__ out, int N) {
    int warp = (blockIdx.x * blockDim.x + threadIdx.x) >> 5;
    int lane = threadIdx.x & 31;
    if (warp >= N) return;
    int d = warp;
    int start = g_rowptr[d], end = g_rowptr[d + 1];
    float adv = g_n2[d].w;
    float a0 = 0.f, a1 = 0.f, ds = 0.f;
    for (int i = start + lane; i < end; i += 32) {
        float4 nv = g_n2[g_col[i]];
        float w = expf(lrelu(nv.z + adv));
        ds += w; a0 += w * nv.x; a1 += w * nv.y;
    }
#pragma unroll
    for (int o = 16; o; o >>= 1) {
        a0 += __shfl_xor_sync(0xffffffffu, a0, o);
        a1 += __shfl_xor_sync(0xffffffffu, a1, o);
        ds += __shfl_xor_sync(0xffffffffu, ds, o);
    }
    if (lane == 0) {
        float inv = 1.f / (ds + 1e-16f);
        out[2 * d]     = a0 * inv + b2[0];
        out[2 * d + 1] = a1 * inv + b2[1];
    }
}

// ---------------------------------------------------------------------------
extern "C" void kernel_launch(void* const* d_in, const int* in_sizes, int n_in,
                              void* d_out, int out_size) {
    const float* x    = (const float*)d_in[0];
    const void*  eidx = d_in[1];
    const float* W1   = (const float*)d_in[2];
    const float* as1  = (const float*)d_in[3];
    const float* ad1  = (const float*)d_in[4];
    const float* b1   = (const float*)d_in[5];
    const float* W2   = (const float*)d_in[6];
    const float* as2  = (const float*)d_in[7];
    const float* ad2  = (const float*)d_in[8];
    const float* b2   = (const float*)d_in[9];

    int N = in_sizes[0] / 128;
    int E = in_sizes[1] / 2;
    int np = (E >> 1) + 1;
    int nb = (N + 1023) / 1024;

    zero_kernel<<<(N + 255) / 256, 256>>>(N);                    // 0
    detect_kernel<<<1, 32>>>((const unsigned int*)eidx);         // 1
    hist_kernel<<<(np + 255) / 256, 256>>>(eidx, E);             // 2
    gemm1a_kernel<<<(N + 127) / 128, 256>>>(x, W1, as1, ad1, N); // 3 <- profiled
    scan1_kernel<<<nb, 1024>>>(N);                               // 4
    scan2_kernel<<<1, 1024>>>(nb, N);                            // 5
    scan3_kernel<<<nb, 1024>>>(N);                               // 6
    fill_kernel<<<(np + 255) / 256, 256>>>(eidx, E);             // 7
    agg1_kernel<<<(N + 3) / 4, 256>>>(b1, W2, as2, ad2, N);      // 8
    agg2_kernel<<<(N + 7) / 8, 256>>>(b2, (float*)d_out, N);     // 9
}

// round 8
// speedup vs baseline: 1.5291x; 1.0925x over previous
#include <cuda_runtime.h>
#include <cuda_fp16.h>
#include <math.h>
#include <stdint.h>

// ---------------------------------------------------------------------------
// ImbalancedGAT R8: fp16 gather table retried in the now-L2-BW-bound
// head-split agg1 (R5's regression was in a latency-bound regime);
// merged init (zero+detect) and scan2->scan3; TC GEMM w/ fp16 stores.
// ---------------------------------------------------------------------------

#define MAXN 65536
#define MAXE 4194304

__device__ __half  g_xw1h[MAXN * 128]; // layer1 transformed features (fp16)
__device__ float   g_as1[MAXN * 2];    // alpha_src layer1 (per head)
__device__ float   g_ad1[MAXN * 2];    // alpha_dst layer1
__device__ float4  g_n2[MAXN];         // {xw2_0, xw2_1, as2, ad2}
__device__ int     g_cnt[MAXN];
__device__ int     g_rowptr[MAXN + 1];
__device__ int     g_cursor[MAXN];
__device__ int     g_col[MAXE];        // CSR (self loop at row head)
__device__ int     g_bsum[64];
__device__ int     g_is64;

__device__ __forceinline__ float lrelu(float x) { return x > 0.f ? x : 0.2f * x; }
__device__ __forceinline__ float elu(float x)   { return x > 0.f ? x : (expf(x) - 1.f); }

// ---- init: zero histogram + dtype detection (merged) ----------------------
__global__ void init_kernel(const unsigned int* ew, int n) {
    int i = blockIdx.x * blockDim.x + threadIdx.x;
    if (i < n) g_cnt[i] = 0;
    if (blockIdx.x == 0 && threadIdx.x < 32) {
        int lane = threadIdx.x;
        int nz = 0;
        for (int k = lane; k < 1024; k += 32) nz += (ew[2 * k + 1] != 0u);
        for (int o = 16; o; o >>= 1) nz += __shfl_xor_sync(0xffffffffu, nz, o);
        if (lane == 0) g_is64 = (nz == 0);  // all-zero high words => int64
    }
}

// ---- mma helpers ----------------------------------------------------------
__device__ __forceinline__ void ldsm_x4(uint32_t addr, uint32_t* r) {
    asm volatile("ldmatrix.sync.aligned.m8n8.x4.shared.b16 {%0,%1,%2,%3}, [%4];"
                 : "=r"(r[0]), "=r"(r[1]), "=r"(r[2]), "=r"(r[3]) : "r"(addr));
}
__device__ __forceinline__ void ldsm_x4_t(uint32_t addr, uint32_t* r) {
    asm volatile("ldmatrix.sync.aligned.m8n8.x4.trans.shared.b16 {%0,%1,%2,%3}, [%4];"
                 : "=r"(r[0]), "=r"(r[1]), "=r"(r[2]), "=r"(r[3]) : "r"(addr));
}
__device__ __forceinline__ void mma16816(float* c, const uint32_t* a, const uint32_t* b) {
    asm volatile("mma.sync.aligned.m16n8k16.row.col.f32.f16.f16.f32 "
                 "{%0,%1,%2,%3}, {%4,%5,%6,%7}, {%8,%9}, {%0,%1,%2,%3};"
                 : "+f"(c[0]), "+f"(c[1]), "+f"(c[2]), "+f"(c[3])
                 : "r"(a[0]), "r"(a[1]), "r"(a[2]), "r"(a[3]), "r"(b[0]), "r"(b[1]));
}

// ---- GEMM1 + alpha1 fused (tensor cores), fp16 direct-store epilogue ------
#define XS_STRIDE 72
#define WS_STRIDE 136
#define XS_BYTES  (128 * XS_STRIDE * 2)
#define SM_BYTES  (XS_BYTES + 64 * WS_STRIDE * 2)

__global__ void __launch_bounds__(256) gemm1a_kernel(
        const float* __restrict__ x, const float* __restrict__ W,
        const float* __restrict__ a_src, const float* __restrict__ a_dst, int N) {
    __shared__ __align__(16) unsigned char smbuf[SM_BYTES];
    __half* xs = (__half*)smbuf;                 // [128][72]
    __half* ws = (__half*)(smbuf + XS_BYTES);    // [64][136]

    int tid  = threadIdx.x;
    int lane = tid & 31;
    int wid  = tid >> 5;
    int row0 = blockIdx.x * 128;
    int R0 = (wid >> 1) * 32;      // warp row base
    int C0 = (wid & 1) * 64;       // warp col base (== head * 64)

    float acc[2][8][4];
#pragma unroll
    for (int mt = 0; mt < 2; mt++)
#pragma unroll
        for (int nt = 0; nt < 8; nt++)
#pragma unroll
            for (int c = 0; c < 4; c++) acc[mt][nt][c] = 0.f;

    uint32_t xs_base = (uint32_t)__cvta_generic_to_shared(xs);
    uint32_t ws_base = (uint32_t)__cvta_generic_to_shared(ws);

    for (int chunk = 0; chunk < 2; chunk++) {
        int k0 = chunk * 64;
#pragma unroll
        for (int j = 0; j < 8; j++) {
            int i = tid + j * 256;
            int r = i >> 4, fc = i & 15;
            int gr = row0 + r; if (gr >= N) gr = N - 1;
            float4 v = *(const float4*)&x[(size_t)gr * 128 + k0 + fc * 4];
            __half2* dst = (__half2*)&xs[r * XS_STRIDE + fc * 4];
            dst[0] = __floats2half2_rn(v.x, v.y);
            dst[1] = __floats2half2_rn(v.z, v.w);
        }
#pragma unroll
        for (int j = 0; j < 8; j++) {
            int i = tid + j * 256;
            int r = i >> 5, fc = i & 31;
            float4 v = *(const float4*)&W[(size_t)(k0 + r) * 128 + fc * 4];
            __half2* dst = (__half2*)&ws[r * WS_STRIDE + fc * 4];
            dst[0] = __floats2half2_rn(v.x, v.y);
            dst[1] = __floats2half2_rn(v.z, v.w);
        }
        __syncthreads();
#pragma unroll
        for (int kt = 0; kt < 4; kt++) {
            uint32_t af[2][4];
#pragma unroll
            for (int mt = 0; mt < 2; mt++) {
                uint32_t addr = xs_base + 2 * ((R0 + mt * 16 + (lane & 15)) * XS_STRIDE
                                               + kt * 16 + (lane >> 4) * 8);
                ldsm_x4(addr, af[mt]);
            }
            uint32_t bf[4][4];
#pragma unroll
            for (int np = 0; np < 4; np++) {
                uint32_t addr = ws_base + 2 * ((kt * 16 + (lane & 15)) * WS_STRIDE
                                               + C0 + np * 16 + (lane >> 4) * 8);
                ldsm_x4_t(addr, bf[np]);
            }
#pragma unroll
            for (int mt = 0; mt < 2; mt++)
#pragma unroll
                for (int np = 0; np < 4; np++) {
                    mma16816(acc[mt][2 * np],     af[mt], &bf[np][0]);
                    mma16816(acc[mt][2 * np + 1], af[mt], &bf[np][2]);
                }
        }
        __syncthreads();
    }

    // ---- alpha epilogue (fp32 from accumulators) ----
    float2 as_l[8], ad_l[8];
#pragma unroll
    for (int nt = 0; nt < 8; nt++) {
        int col = C0 + nt * 8 + (lane & 3) * 2;
        as_l[nt] = *(const float2*)&a_src[col];
        ad_l[nt] = *(const float2*)&a_dst[col];
    }
    int head = wid & 1;
#pragma unroll
    for (int mt = 0; mt < 2; mt++)
#pragma unroll
        for (int rh = 0; rh < 2; rh++) {
            float ps = 0.f, pd = 0.f;
#pragma unroll
            for (int nt = 0; nt < 8; nt++) {
                float v0 = acc[mt][nt][2 * rh], v1 = acc[mt][nt][2 * rh + 1];
                ps += v0 * as_l[nt].x + v1 * as_l[nt].y;
                pd += v0 * ad_l[nt].x + v1 * ad_l[nt].y;
            }
            ps += __shfl_xor_sync(0xffffffffu, ps, 1);
            pd += __shfl_xor_sync(0xffffffffu, pd, 1);
            ps += __shfl_xor_sync(0xffffffffu, ps, 2);
            pd += __shfl_xor_sync(0xffffffffu, pd, 2);
            if ((lane & 3) == 0) {
                int row = row0 + R0 + mt * 16 + rh * 8 + (lane >> 2);
                if (row < N) {
                    g_as1[2 * row + head] = ps;
                    g_ad1[2 * row + head] = pd;
                }
            }
        }

    // ---- direct fp16 stores (half2 per fragment pair) ----
#pragma unroll
    for (int mt = 0; mt < 2; mt++)
#pragma unroll
        for (int nt = 0; nt < 8; nt++) {
            int r  = row0 + R0 + mt * 16 + (lane >> 2);
            int cc = C0 + nt * 8 + (lane & 3) * 2;
            if (r < N)
                *(__half2*)&g_xw1h[(size_t)r * 128 + cc] =
                    __floats2half2_rn(acc[mt][nt][0], acc[mt][nt][1]);
            if (r + 8 < N)
                *(__half2*)&g_xw1h[(size_t)(r + 8) * 128 + cc] =
                    __floats2half2_rn(acc[mt][nt][2], acc[mt][nt][3]);
        }
}

// ---- CSR build: 2 edges per thread ----------------------------------------
__global__ void hist_kernel(const void* e, int E) {
    int t = blockIdx.x * blockDim.x + threadIdx.x;
    int np = E >> 1;
    if (t < np) {
        int d0, d1;
        if (g_is64) {
            longlong2 v = ((const longlong2*)((const char*)e + (size_t)E * 8))[t];
            d0 = (int)v.x; d1 = (int)v.y;
        } else {
            int2 v = ((const int2*)((const char*)e + (size_t)E * 4))[t];
            d0 = v.x; d1 = v.y;
        }
        atomicAdd(&g_cnt[d0], 1);
        atomicAdd(&g_cnt[d1], 1);
    } else if (t == np && (E & 1)) {
        int d = g_is64 ? (int)((const long long*)e)[(size_t)E + E - 1]
                       : ((const int*)e)[(size_t)E + E - 1];
        atomicAdd(&g_cnt[d], 1);
    }
}

// ---- scan1: per-block inclusive scan (+1/node folds self-loop) ------------
__global__ void scan1_kernel(int n) {
    __shared__ int wsum[32];
    int t = threadIdx.x, lane = t & 31, wid = t >> 5;
    int idx = blockIdx.x * 1024 + t;
    int v = (idx < n) ? (g_cnt[idx] + 1) : 0;
    int s = v;
#pragma unroll
    for (int o = 1; o < 32; o <<= 1) {
        int u = __shfl_up_sync(0xffffffffu, s, o);
        if (lane >= o) s += u;
    }
    if (lane == 31) wsum[wid] = s;
    __syncthreads();
    if (wid == 0) {
        int w = wsum[lane];
#pragma unroll
        for (int o = 1; o < 32; o <<= 1) {
            int u = __shfl_up_sync(0xffffffffu, w, o);
            if (lane >= o) w += u;
        }
        wsum[lane] = w;
    }
    __syncthreads();
    int incl = s + (wid ? wsum[wid - 1] : 0);
    if (idx < n) g_cursor[idx] = incl;         // block-local inclusive (tmp)
    if (t == 0) g_bsum[blockIdx.x] = wsum[31]; // block total
}

// ---- scan3: block offsets (redundant 64-wide scan per block) + finalize ---
__global__ void scan3_kernel(int n, int nb) {
    __shared__ int sb[64];
    int t = threadIdx.x;
    if (t < 64) sb[t] = (t < nb) ? g_bsum[t] : 0;
    __syncthreads();
#pragma unroll
    for (int o = 1; o < 64; o <<= 1) {
        int v = (t < 64 && t >= o) ? sb[t - o] : 0;
        __syncthreads();
        if (t < 64) sb[t] += v;
        __syncthreads();
    }
    int idx = blockIdx.x * 1024 + t;
    if (idx >= n) return;
    int off = blockIdx.x ? sb[blockIdx.x - 1] : 0;
    int v = g_cnt[idx] + 1;
    int incl = g_cursor[idx];
    int excl = off + incl - v;
    g_rowptr[idx] = excl;
    g_col[excl]   = idx;        // self loop at row head
    g_cursor[idx] = excl + 1;
    if (idx == n - 1) g_rowptr[n] = excl + v;
}

__global__ void fill_kernel(const void* e, int E) {
    int t = blockIdx.x * blockDim.x + threadIdx.x;
    int np = E >> 1;
    if (t < np) {
        int s0, s1, d0, d1;
        if (g_is64) {
            longlong2 sv = ((const longlong2*)e)[t];
            longlong2 dv = ((const longlong2*)((const char*)e + (size_t)E * 8))[t];
            s0 = (int)sv.x; s1 = (int)sv.y; d0 = (int)dv.x; d1 = (int)dv.y;
        } else {
            int2 sv = ((const int2*)e)[t];
            int2 dv = ((const int2*)((const char*)e + (size_t)E * 4))[t];
            s0 = sv.x; s1 = sv.y; d0 = dv.x; d1 = dv.y;
        }
        g_col[atomicAdd(&g_cursor[d0], 1)] = s0;
        g_col[atomicAdd(&g_cursor[d1], 1)] = s1;
    } else if (t == np && (E & 1)) {
        int s, d;
        if (g_is64) { s = (int)((const long long*)e)[E - 1];
                      d = (int)((const long long*)e)[(size_t)E + E - 1]; }
        else        { s = ((const int*)e)[E - 1];
                      d = ((const int*)e)[(size_t)E + E - 1]; }
        g_col[atomicAdd(&g_cursor[d], 1)] = s;
    }
}

// ---- Layer1 aggregation: 2 warps per node (one per head), fp16 gathers ----
__global__ void __launch_bounds__(256) agg1_kernel(
        const float* __restrict__ b1, const float* __restrict__ W2,
        const float* __restrict__ a_src2, const float* __restrict__ a_dst2, int N) {
    __shared__ int   s_sh[8][32];
    __shared__ float w_sh[8][32];
    __shared__ float p_sh[8][2];
    int wip  = threadIdx.x >> 5;
    int lane = threadIdx.x & 31;
    int d    = blockIdx.x * 4 + (wip >> 1);
    int head = wip & 1;
    bool valid = d < N;

    if (valid) {
        int start = g_rowptr[d], end = g_rowptr[d + 1];
        float adv = g_ad1[2 * d + head];
        int grp = lane >> 4;
        int cq  = (lane & 15) * 4;
        const __half* bx = g_xw1h + head * 64 + cq;
        float4 accA = make_float4(0.f, 0.f, 0.f, 0.f);
        float4 accB = make_float4(0.f, 0.f, 0.f, 0.f);
        float ds = 0.f;
        int*   ss = s_sh[wip];
        float* ws = w_sh[wip];

        for (int b0 = start; b0 < end; b0 += 32) {
            int i = b0 + lane;
            int s = d; float w = 0.f;
            if (i < end) {
                s = g_col[i];
                w = expf(lrelu(g_as1[2 * s + head] + adv));  // no max: bounded
                ds += w;
            }
            __syncwarp();
            ss[lane] = s; ws[lane] = w;
            __syncwarp();
            int cnt = end - b0; if (cnt > 32) cnt = 32;
            cnt = (cnt + 3) & ~3;                  // pad: w=0 entries no-op
            for (int g = 0; g < cnt; g += 4) {
                int4   s4 = *(const int4*)&ss[g];
                float4 w4 = *(const float4*)&ws[g];
                int   sA = grp ? s4.y : s4.x;
                int   sB = grp ? s4.w : s4.z;
                float wA = grp ? w4.y : w4.x;
                float wB = grp ? w4.w : w4.z;
                uint2 rA = *(const uint2*)&bx[(size_t)sA * 128];
                uint2 rB = *(const uint2*)&bx[(size_t)sB * 128];
                float2 vA0 = __half22float2(*(__half2*)&rA.x);
                float2 vA1 = __half22float2(*(__half2*)&rA.y);
                float2 vB0 = __half22float2(*(__half2*)&rB.x);
                float2 vB1 = __half22float2(*(__half2*)&rB.y);
                accA.x += wA * vA0.x; accA.y += wA * vA0.y;
                accA.z += wA * vA1.x; accA.w += wA * vA1.y;
                accB.x += wB * vB0.x; accB.y += wB * vB0.y;
                accB.z += wB * vB1.x; accB.w += wB * vB1.y;
            }
        }
        // merge the two 16-lane groups
        accA.x += accB.x; accA.y += accB.y; accA.z += accB.z; accA.w += accB.w;
        accA.x += __shfl_xor_sync(0xffffffffu, accA.x, 16);
        accA.y += __shfl_xor_sync(0xffffffffu, accA.y, 16);
        accA.z += __shfl_xor_sync(0xffffffffu, accA.z, 16);
        accA.w += __shfl_xor_sync(0xffffffffu, accA.w, 16);
#pragma unroll
        for (int o = 16; o; o >>= 1)
            ds += __shfl_xor_sync(0xffffffffu, ds, o);
        float inv = 1.f / (ds + 1e-16f);
        int cg = head * 64 + cq;
        float4 bb = *(const float4*)&b1[cg];
        float hx = elu(accA.x * inv + bb.x);
        float hy = elu(accA.y * inv + bb.y);
        float hz = elu(accA.z * inv + bb.z);
        float hw = elu(accA.w * inv + bb.w);
        // fused layer2 transform partials over this head's channels
        float p0 = hx * W2[2*cg]   + hy * W2[2*(cg+1)]   + hz * W2[2*(cg+2)]   + hw * W2[2*(cg+3)];
        float p1 = hx * W2[2*cg+1] + hy * W2[2*(cg+1)+1] + hz * W2[2*(cg+2)+1] + hw * W2[2*(cg+3)+1];
#pragma unroll
        for (int o = 1; o < 16; o <<= 1) {
            p0 += __shfl_xor_sync(0xffffffffu, p0, o);
            p1 += __shfl_xor_sync(0xffffffffu, p1, o);
        }
        if (lane == 0) { p_sh[wip][0] = p0; p_sh[wip][1] = p1; }
    }
    __syncthreads();
    if (valid && head == 0 && lane == 0) {
        float q0 = p_sh[wip][0] + p_sh[wip + 1][0];
        float q1 = p_sh[wip][1] + p_sh[wip + 1][1];
        float4 nv;
        nv.x = q0; nv.y = q1;
        nv.z = q0 * a_src2[0] + q1 * a_src2[1];
        nv.w = q0 * a_dst2[0] + q1 * a_dst2[1];
        g_n2[d] = nv;
    }
}

// ---- Layer2 aggregation: warp per dst node, single pass -------------------
__global__ void agg2_kernel(const float* __restrict__ b2, float* __restrict__ out, int N) {
    int warp = (blockIdx.x * blockDim.x + threadIdx.x) >> 5;
    int lane = threadIdx.x & 31;
    if (warp >= N) return;
    int d = warp;
    int start = g_rowptr[d], end = g_rowptr[d + 1];
    float adv = g_n2[d].w;
    float a0 = 0.f, a1 = 0.f, ds = 0.f;
    for (int i = start + lane; i < end; i += 32) {
        float4 nv = g_n2[g_col[i]];
        float w = expf(lrelu(nv.z + adv));
        ds += w; a0 += w * nv.x; a1 += w * nv.y;
    }
#pragma unroll
    for (int o = 16; o; o >>= 1) {
        a0 += __shfl_xor_sync(0xffffffffu, a0, o);
        a1 += __shfl_xor_sync(0xffffffffu, a1, o);
        ds += __shfl_xor_sync(0xffffffffu, ds, o);
    }
    if (lane == 0) {
        float inv = 1.f / (ds + 1e-16f);
        out[2 * d]     = a0 * inv + b2[0];
        out[2 * d + 1] = a1 * inv + b2[1];
    }
}

// ---------------------------------------------------------------------------
extern "C" void kernel_launch(void* const* d_in, const int* in_sizes, int n_in,
                              void* d_out, int out_size) {
    const float* x    = (const float*)d_in[0];
    const void*  eidx = d_in[1];
    const float* W1   = (const float*)d_in[2];
    const float* as1  = (const float*)d_in[3];
    const float* ad1  = (const float*)d_in[4];
    const float* b1   = (const float*)d_in[5];
    const float* W2   = (const float*)d_in[6];
    const float* as2  = (const float*)d_in[7];
    const float* ad2  = (const float*)d_in[8];
    const float* b2   = (const float*)d_in[9];

    int N = in_sizes[0] / 128;
    int E = in_sizes[1] / 2;
    int np = (E >> 1) + 1;
    int nb = (N + 1023) / 1024;

    init_kernel<<<(N + 255) / 256, 256>>>((const unsigned int*)eidx, N); // 0
    hist_kernel<<<(np + 255) / 256, 256>>>(eidx, E);                     // 1
    scan1_kernel<<<nb, 1024>>>(N);                                       // 2
    gemm1a_kernel<<<(N + 127) / 128, 256>>>(x, W1, as1, ad1, N);         // 3 <- profiled
    scan3_kernel<<<nb, 1024>>>(N, nb);                                   // 4
    fill_kernel<<<(np + 255) / 256, 256>>>(eidx, E);                     // 5
    agg1_kernel<<<(N + 3) / 4, 256>>>(b1, W2, as2, ad2, N);              // 6
    agg2_kernel<<<(N + 7) / 8, 256>>>(b2, (float*)d_out, N);             // 7
}